// round 6
// baseline (speedup 1.0000x reference)
#include <cuda_runtime.h>
#include <cuda_fp16.h>
#include <math.h>
#include <stdint.h>

#define KCODES 512
#define CDIM   64
#define NPIX   131072
#define HW     4096
#define CHW    262144
#define TILE_M 256
#define NT2    (NPIX/TILE_M)    // 512 tiles
#define GRID   148
#define CBP    72               // fp16 row pad
#define XNP    68               // fp32 xn row pad
#define CAP    16
#define MARGIN 4e-3f

// __device__ scratch (allocation-free rule)
__device__ float g_cbn[KCODES*CDIM];   // normalized codebook fp32
__device__ __half g_cbh[KCODES*CDIM];  // normalized codebook fp16
__device__ float g_cc[KCODES];         // ||cbn_k||^2

// ---------------- smem layout ----------------
#define OFF_B    0                 // 512*72*2 = 73728
#define OFF_A    73728             // 256*72*2 = 36864
#define OFF_XN   110592            // 256*68*4 = 69632
#define OFF_CC   180224            // 2048
#define OFF_LIST 182272            // 256*16*4 = 16384
#define OFF_CNT  198656            // 1024
#define SM_TOTAL 199680

// ---------------- helpers ----------------
__device__ __forceinline__ uint32_t smem_u32(const void* p) {
    uint32_t a;
    asm("{ .reg .u64 t; cvta.to.shared.u64 t, %1; cvt.u32.u64 %0, t; }" : "=r"(a) : "l"(p));
    return a;
}
__device__ __forceinline__ void ldsm4(uint32_t* r, uint32_t addr) {
    asm volatile("ldmatrix.sync.aligned.m8n8.x4.shared.b16 {%0,%1,%2,%3}, [%4];"
                 : "=r"(r[0]), "=r"(r[1]), "=r"(r[2]), "=r"(r[3]) : "r"(addr));
}
__device__ __forceinline__ void mma16816(float* c, const uint32_t* a,
                                         uint32_t b0, uint32_t b1) {
    asm volatile("mma.sync.aligned.m16n8k16.row.col.f32.f16.f16.f32 "
                 "{%0,%1,%2,%3}, {%4,%5,%6,%7}, {%8,%9}, {%0,%1,%2,%3};"
                 : "+f"(c[0]), "+f"(c[1]), "+f"(c[2]), "+f"(c[3])
                 : "r"(a[0]), "r"(a[1]), "r"(a[2]), "r"(a[3]), "r"(b0), "r"(b1));
}

// ---------------------------------------------------------------------------
// Prep: normalize codebook -> fp32 + fp16 copies + ||c||^2
// ---------------------------------------------------------------------------
__global__ void prep_kernel(const float* __restrict__ cb) {
    int k = blockIdx.x * blockDim.x + threadIdx.x;
    if (k >= KCODES) return;
    float row[CDIM];
    float ss = 0.f;
    #pragma unroll
    for (int c = 0; c < CDIM; ++c) { row[c] = cb[k*CDIM + c]; ss += row[c]*row[c]; }
    float inv = 1.0f / fmaxf(sqrtf(ss), 1e-12f);
    float cc = 0.f;
    #pragma unroll
    for (int c = 0; c < CDIM; ++c) {
        float v = row[c] * inv;
        g_cbn[k*CDIM + c] = v;
        g_cbh[k*CDIM + c] = __float2half_rn(v);
        cc += v*v;
    }
    g_cc[k] = cc;
}

// ---------------------------------------------------------------------------
// Main: persistent CTAs (grid=148). Codebook fp16 loaded to smem ONCE.
// Per tile (256 pixels): build A, fp16 mma.sync prune (each warp: 32 rows,
// B fragments reused across 2 row-tiles), exact fp32 rescore, write out.
// ---------------------------------------------------------------------------
__global__ void __launch_bounds__(256, 1)
vq_kernel(const float* __restrict__ x, float* __restrict__ out, int write_idx) {
    extern __shared__ char sm[];
    __half* Bh = (__half*)(sm + OFF_B);
    __half* Ah = (__half*)(sm + OFF_A);
    float*  XN = (float*)(sm + OFF_XN);
    float*  CC = (float*)(sm + OFF_CC);
    int*  LIST = (int*)(sm + OFF_LIST);
    int*   CNT = (int*)(sm + OFF_CNT);

    int tid = threadIdx.x, lane = tid & 31, wid = tid >> 5;

    // ---- one-time: fp16 codebook + cc into smem ----
    {
        const uint4* src = (const uint4*)g_cbh;   // 4096 x 16B
        #pragma unroll 4
        for (int i = tid; i < 4096; i += 256) {
            int n = i >> 3, q = i & 7;
            *(uint4*)(Bh + n*CBP + q*8) = src[i];
        }
        for (int i = tid; i < KCODES; i += 256) CC[i] = g_cc[i];
    }

    uint32_t smb = smem_u32(sm);
    uint32_t AhB = smb + OFF_A, BhB = smb + OFF_B;

    for (int tile = blockIdx.x; tile < NT2; tile += GRID) {
        // ---- reset counters + build A (1 thread = 1 row) ----
        __syncthreads();        // prior tile's rescore done before overwrite
        CNT[tid] = 0;
        {
            int n = tile*TILE_M + tid;
            const float* xb = x + (size_t)(n >> 12)*CHW + (n & 4095);
            float v[CDIM];
            float ss = 0.f;
            #pragma unroll
            for (int c = 0; c < CDIM; ++c) { v[c] = xb[(size_t)c*HW]; ss += v[c]*v[c]; }
            float inv = 1.0f / fmaxf(sqrtf(ss), 1e-12f);
            #pragma unroll
            for (int c = 0; c < CDIM; ++c) { v[c] *= inv; XN[tid*XNP + c] = v[c]; }
            #pragma unroll
            for (int i = 0; i < 32; ++i)
                *(__half2*)(Ah + tid*CBP + 2*i) = __floats2half2_rn(v[2*i], v[2*i+1]);
        }
        __syncthreads();

        // ---- GEMM prune: warp handles rows r0..r0+31 (2 row-tiles of 16) ----
        {
            int r0 = wid * 32;
            uint32_t a[2][4][4];
            {
                int rsel = lane & 15, kh = (lane >> 4) << 3;
                #pragma unroll
                for (int rt = 0; rt < 2; ++rt)
                    #pragma unroll
                    for (int j = 0; j < 4; ++j) {
                        uint32_t ad = AhB + (uint32_t)(((r0 + rt*16 + rsel)*CBP + 16*j + kh) * 2);
                        ldsm4(a[rt][j], ad);
                    }
            }
            int noff = (lane & 7) + ((lane >> 4) << 3);
            int kadd = ((lane >> 3) & 1) << 3;
            int rsub = lane >> 2;
            float best_lo[2] = {1e30f, 1e30f}, best_hi[2] = {1e30f, 1e30f};

            for (int chunk = 0; chunk < 8; ++chunk) {
                float C[2][8][4];
                #pragma unroll
                for (int rt = 0; rt < 2; ++rt)
                    #pragma unroll
                    for (int t = 0; t < 8; ++t)
                        { C[rt][t][0]=0.f; C[rt][t][1]=0.f; C[rt][t][2]=0.f; C[rt][t][3]=0.f; }

                #pragma unroll
                for (int j = 0; j < 4; ++j) {
                    #pragma unroll
                    for (int tp = 0; tp < 4; ++tp) {
                        int n0 = chunk*64 + tp*16;
                        uint32_t bad = BhB + (uint32_t)(((n0 + noff)*CBP + 16*j + kadd) * 2);
                        uint32_t b[4];
                        ldsm4(b, bad);
                        #pragma unroll
                        for (int rt = 0; rt < 2; ++rt) {
                            mma16816(C[rt][2*tp],   a[rt][j], b[0], b[1]);
                            mma16816(C[rt][2*tp+1], a[rt][j], b[2], b[3]);
                        }
                    }
                }

                int code0base = chunk*64 + 2*(lane & 3);
                #pragma unroll
                for (int rt = 0; rt < 2; ++rt) {
                    #pragma unroll
                    for (int t = 0; t < 8; ++t) {
                        int c0 = code0base + t*8;
                        float cc0 = CC[c0], cc1 = CC[c0+1];
                        C[rt][t][0] = fmaf(-2.f, C[rt][t][0], cc0);
                        C[rt][t][1] = fmaf(-2.f, C[rt][t][1], cc1);
                        C[rt][t][2] = fmaf(-2.f, C[rt][t][2], cc0);
                        C[rt][t][3] = fmaf(-2.f, C[rt][t][3], cc1);
                        best_lo[rt] = fminf(best_lo[rt], fminf(C[rt][t][0], C[rt][t][1]));
                        best_hi[rt] = fminf(best_hi[rt], fminf(C[rt][t][2], C[rt][t][3]));
                    }
                    best_lo[rt] = fminf(best_lo[rt], __shfl_xor_sync(0xffffffffu, best_lo[rt], 1));
                    best_lo[rt] = fminf(best_lo[rt], __shfl_xor_sync(0xffffffffu, best_lo[rt], 2));
                    best_hi[rt] = fminf(best_hi[rt], __shfl_xor_sync(0xffffffffu, best_hi[rt], 1));
                    best_hi[rt] = fminf(best_hi[rt], __shfl_xor_sync(0xffffffffu, best_hi[rt], 2));
                    float thr_lo = best_lo[rt] + MARGIN, thr_hi = best_hi[rt] + MARGIN;
                    int row_lo = r0 + rt*16 + rsub, row_hi = row_lo + 8;

                    #pragma unroll
                    for (int t = 0; t < 8; ++t) {
                        int c0 = code0base + t*8;
                        if (C[rt][t][0] <= thr_lo) { int p = atomicAdd(&CNT[row_lo], 1); if (p < CAP) LIST[row_lo*CAP + p] = c0;   }
                        if (C[rt][t][1] <= thr_lo) { int p = atomicAdd(&CNT[row_lo], 1); if (p < CAP) LIST[row_lo*CAP + p] = c0+1; }
                        if (C[rt][t][2] <= thr_hi) { int p = atomicAdd(&CNT[row_hi], 1); if (p < CAP) LIST[row_hi*CAP + p] = c0;   }
                        if (C[rt][t][3] <= thr_hi) { int p = atomicAdd(&CNT[row_hi], 1); if (p < CAP) LIST[row_hi*CAP + p] = c0+1; }
                    }
                }
            }
        }
        __syncthreads();

        // ---- exact fp32 rescore (1 thread = 1 row) + output ----
        {
            int r = tid;
            int n = tile*TILE_M + r;
            int cn = CNT[r];
            bool ovf = (cn > CAP);
            if (cn > CAP) cn = CAP;

            const float4* x4 = (const float4*)(XN + r*XNP);
            float bd = 1e30f;
            int   bk = 0x7fffffff;

            if (!ovf) {
                for (int i = 0; i < cn; ++i) {
                    int k = LIST[r*CAP + i];
                    const float4* cb4 = (const float4*)(g_cbn + (size_t)k*CDIM);
                    float d0 = 0.f, d1 = 0.f;
                    #pragma unroll
                    for (int q = 0; q < 16; q += 2) {
                        float4 xa = x4[q],   ca = cb4[q];
                        float4 xb2 = x4[q+1], cb2 = cb4[q+1];
                        d0 = fmaf(xa.x, ca.x, d0);  d0 = fmaf(xa.y, ca.y, d0);
                        d0 = fmaf(xa.z, ca.z, d0);  d0 = fmaf(xa.w, ca.w, d0);
                        d1 = fmaf(xb2.x, cb2.x, d1); d1 = fmaf(xb2.y, cb2.y, d1);
                        d1 = fmaf(xb2.z, cb2.z, d1); d1 = fmaf(xb2.w, cb2.w, d1);
                    }
                    float d = fmaf(-2.f, d0 + d1, CC[k]);
                    if (d < bd || (d == bd && k < bk)) { bd = d; bk = k; }
                }
            } else {
                for (int k = 0; k < KCODES; ++k) {
                    const float4* cb4 = (const float4*)(g_cbn + (size_t)k*CDIM);
                    float d0 = 0.f;
                    #pragma unroll
                    for (int q = 0; q < 16; ++q) {
                        float4 xa = x4[q], ca = cb4[q];
                        d0 = fmaf(xa.x, ca.x, d0); d0 = fmaf(xa.y, ca.y, d0);
                        d0 = fmaf(xa.z, ca.z, d0); d0 = fmaf(xa.w, ca.w, d0);
                    }
                    float d = fmaf(-2.f, d0, CC[k]);
                    if (d < bd) { bd = d; bk = k; }   // ascending k: strict < = first-min
                }
            }

            float* ob = out + (size_t)(n >> 12)*CHW + (n & 4095);
            const float4* cbb = (const float4*)(g_cbn + (size_t)bk*CDIM);
            #pragma unroll
            for (int q = 0; q < 16; ++q) {
                float4 vv = cbb[q];
                int c = q * 4;
                ob[(size_t)(c+0)*HW] = vv.x;
                ob[(size_t)(c+1)*HW] = vv.y;
                ob[(size_t)(c+2)*HW] = vv.z;
                ob[(size_t)(c+3)*HW] = vv.w;
            }
            if (write_idx)
                out[(size_t)NPIX*CDIM + n] = (float)bk;
        }
    }
}

// ---------------------------------------------------------------------------
extern "C" void kernel_launch(void* const* d_in, const int* in_sizes, int n_in,
                              void* d_out, int out_size) {
    const float* x;
    const float* cb;
    if (in_sizes[0] == KCODES*CDIM) {
        cb = (const float*)d_in[0];
        x  = (const float*)d_in[1];
    } else {
        x  = (const float*)d_in[0];
        cb = (const float*)d_in[1];
    }
    float* out = (float*)d_out;

    prep_kernel<<<2, 256>>>(cb);

    cudaFuncSetAttribute(vq_kernel, cudaFuncAttributeMaxDynamicSharedMemorySize, SM_TOTAL);
    int write_idx = (out_size >= NPIX*CDIM + NPIX) ? 1 : 0;
    vq_kernel<<<GRID, 256, SM_TOTAL>>>(x, out, write_idx);
}